// round 7
// baseline (speedup 1.0000x reference)
#include <cuda_runtime.h>
#include <cstdint>

#define Bdim 4
#define Tdim 256
#define Sdim 256
#define Ddim 512

// Scratch (allocation-free rule: __device__ globals)
__device__ float g_wq[Bdim * Tdim * Ddim];    // 2 MB
__device__ float g_uh[Bdim * Sdim * Ddim];    // 2 MB
__device__ float g_sc[Bdim * Tdim * Sdim];    // 1 MB (scores, then attn)
__device__ float g_pre1[Bdim * Sdim * Ddim];  // 2 MB  ctx @ Wout_top
__device__ float g_pre2[Bdim * Tdim * Ddim];  // 2 MB  output @ Wout_bot + bout

__device__ __forceinline__ float tanh_fast(float x) {
    float y;
    asm("tanh.approx.f32 %0, %1;" : "=f"(y) : "f"(x));
    return y;
}

__device__ __forceinline__ uint32_t f2tf32(float x) {
    uint32_t y;
    asm("cvt.rna.tf32.f32 %0, %1;" : "=r"(y) : "f"(x));
    return y;
}

__device__ __forceinline__ void mma_tf32(float* d, const uint32_t* a,
                                         const uint32_t* b) {
    asm volatile(
        "mma.sync.aligned.m16n8k8.row.col.f32.tf32.tf32.f32 "
        "{%0,%1,%2,%3}, {%4,%5,%6,%7}, {%8,%9}, {%0,%1,%2,%3};"
        : "+f"(d[0]), "+f"(d[1]), "+f"(d[2]), "+f"(d[3])
        : "r"(a[0]), "r"(a[1]), "r"(a[2]), "r"(a[3]), "r"(b[0]), "r"(b[1]));
}

#define CP16(dst, src) \
    asm volatile("cp.async.cg.shared.global [%0], [%1], 16;" \
                 :: "r"(dst), "l"(src) : "memory")
#define CP_COMMIT() asm volatile("cp.async.commit_group;" ::: "memory")
#define CP_WAIT2()  asm volatile("cp.async.wait_group 2;" ::: "memory")

#define STAGES 4
#define LDA 20
#define LDB 72
#define ABYTES (64 * LDA * 4)
#define BBYTES (16 * LDB * 4)

// ---------------------------------------------------------------------------
// 128-thread core: 64x64 tile, 4 warps (2x2), warp tile 32x32.
// ---------------------------------------------------------------------------
__device__ __forceinline__ void gemm_core(
    const float* __restrict__ A, int lda,
    const float* __restrict__ B, int ldb, int K,
    const float* __restrict__ bias, const float* __restrict__ addend,
    float* __restrict__ C, int N, int m0, int n0)
{
    __shared__ float As[STAGES][64 * LDA];
    __shared__ float Bs[STAGES][16 * LDB];

    const int tid = threadIdx.x;
    const int wid = tid >> 5;
    const int lane = tid & 31;
    const int g = lane >> 2;
    const int tig = lane & 3;
    const int warp_m = wid >> 1;
    const int warp_n = wid & 1;

    const int ar = tid >> 1;
    const int ak = (tid & 1) << 3;
    const int br = tid >> 3;
    const int bc = (tid & 7) << 3;

    uint32_t as_s = (uint32_t)__cvta_generic_to_shared(&As[0][0]);
    uint32_t bs_s = (uint32_t)__cvta_generic_to_shared(&Bs[0][0]);

    const int NT = K >> 4;

    float acc[2][4][4];
#pragma unroll
    for (int i = 0; i < 2; i++)
#pragma unroll
        for (int j = 0; j < 4; j++)
#pragma unroll
            for (int q = 0; q < 4; q++) acc[i][j][q] = 0.f;

    auto issue = [&](int stage, int kt) {
        const int kg = kt << 4;
        const float* s0 = A + (long)(m0 + ar) * lda + kg + ak;
        uint32_t d0 = as_s + stage * ABYTES + (ar * LDA + ak) * 4;
        CP16(d0, s0);
        CP16(d0 + 16, s0 + 4);
        const float* sb = B + (long)(kg + br) * ldb + n0 + bc;
        uint32_t db = bs_s + stage * BBYTES + (br * LDB + bc) * 4;
        CP16(db, sb);
        CP16(db + 16, sb + 4);
    };

#pragma unroll
    for (int p = 0; p < STAGES - 1; p++) {
        if (p < NT) issue(p, p);
        CP_COMMIT();
    }

    for (int t = 0; t < NT; t++) {
        const int st = t & (STAGES - 1);
        CP_WAIT2();
        __syncthreads();

        if (t + STAGES - 1 < NT) issue((t + STAGES - 1) & (STAGES - 1), t + STAGES - 1);
        CP_COMMIT();

        const float* as = As[st];
        const float* bs = Bs[st];
        const int mb = warp_m * 32;
        const int nb = warp_n * 32;
#pragma unroll
        for (int ks = 0; ks < 2; ks++) {
            const int k0 = ks << 3;
            uint32_t a[2][4], b[4][2];
#pragma unroll
            for (int im = 0; im < 2; im++) {
                const float* ap = as + (mb + im * 16 + g) * LDA;
                a[im][0] = f2tf32(ap[k0 + tig]);
                a[im][1] = f2tf32(ap[8 * LDA + k0 + tig]);
                a[im][2] = f2tf32(ap[k0 + tig + 4]);
                a[im][3] = f2tf32(ap[8 * LDA + k0 + tig + 4]);
            }
#pragma unroll
            for (int in = 0; in < 4; in++) {
                const int nc = nb + in * 8 + g;
                b[in][0] = f2tf32(bs[(k0 + tig) * LDB + nc]);
                b[in][1] = f2tf32(bs[(k0 + tig + 4) * LDB + nc]);
            }
#pragma unroll
            for (int im = 0; im < 2; im++)
#pragma unroll
                for (int in = 0; in < 4; in++)
                    mma_tf32(acc[im][in], a[im], b[in]);
        }
        __syncthreads();
    }

    const int mb = warp_m * 32;
    const int nb = warp_n * 32;
#pragma unroll
    for (int im = 0; im < 2; im++) {
#pragma unroll
        for (int in = 0; in < 4; in++) {
            const int row = m0 + mb + im * 16 + g;
            const int col = n0 + nb + in * 8 + tig * 2;
            float bx = 0.f, by = 0.f;
            if (bias) { bx = bias[col]; by = bias[col + 1]; }
            float2 o0 = make_float2(acc[im][in][0] + bx, acc[im][in][1] + by);
            float2 o1 = make_float2(acc[im][in][2] + bx, acc[im][in][3] + by);
            if (addend) {
                const float2 r0 = *(const float2*)&addend[(long)row * N + col];
                const float2 r1 = *(const float2*)&addend[(long)(row + 8) * N + col];
                o0.x += r0.x; o0.y += r0.y;
                o1.x += r1.x; o1.y += r1.y;
            }
            *(float2*)&C[(long)row * N + col] = o0;
            *(float2*)&C[(long)(row + 8) * N + col] = o1;
        }
    }
}

// ---------------------------------------------------------------------------
// 256-thread core: 64x64 tile, 8 warps (2m x 4n), warp tile 32x16. (gemm_fin)
// ---------------------------------------------------------------------------
__device__ __forceinline__ void gemm_core_256(
    const float* __restrict__ A, int lda,
    const float* __restrict__ B, int ldb, int K,
    const float* __restrict__ addend,
    float* __restrict__ C, int N, int m0, int n0)
{
    __shared__ float As[STAGES][64 * LDA];
    __shared__ float Bs[STAGES][16 * LDB];

    const int tid = threadIdx.x;
    const int wid = tid >> 5;
    const int lane = tid & 31;
    const int g = lane >> 2;
    const int tig = lane & 3;
    const int warp_m = wid >> 2;
    const int warp_n = wid & 3;

    const int ar = tid >> 2;
    const int ak = (tid & 3) << 2;
    const int br = tid >> 4;
    const int bc = (tid & 15) << 2;

    uint32_t as_s = (uint32_t)__cvta_generic_to_shared(&As[0][0]);
    uint32_t bs_s = (uint32_t)__cvta_generic_to_shared(&Bs[0][0]);

    const int NT = K >> 4;

    float acc[2][2][4];
#pragma unroll
    for (int i = 0; i < 2; i++)
#pragma unroll
        for (int j = 0; j < 2; j++)
#pragma unroll
            for (int q = 0; q < 4; q++) acc[i][j][q] = 0.f;

    auto issue = [&](int stage, int kt) {
        const int kg = kt << 4;
        const float* s0 = A + (long)(m0 + ar) * lda + kg + ak;
        uint32_t d0 = as_s + stage * ABYTES + (ar * LDA + ak) * 4;
        CP16(d0, s0);
        const float* sb = B + (long)(kg + br) * ldb + n0 + bc;
        uint32_t db = bs_s + stage * BBYTES + (br * LDB + bc) * 4;
        CP16(db, sb);
    };

#pragma unroll
    for (int p = 0; p < STAGES - 1; p++) {
        if (p < NT) issue(p, p);
        CP_COMMIT();
    }

    for (int t = 0; t < NT; t++) {
        const int st = t & (STAGES - 1);
        CP_WAIT2();
        __syncthreads();

        if (t + STAGES - 1 < NT) issue((t + STAGES - 1) & (STAGES - 1), t + STAGES - 1);
        CP_COMMIT();

        const float* as = As[st];
        const float* bs = Bs[st];
        const int mb = warp_m * 32;
        const int nb = warp_n * 16;
#pragma unroll
        for (int ks = 0; ks < 2; ks++) {
            const int k0 = ks << 3;
            uint32_t a[2][4], b[2][2];
#pragma unroll
            for (int im = 0; im < 2; im++) {
                const float* ap = as + (mb + im * 16 + g) * LDA;
                a[im][0] = f2tf32(ap[k0 + tig]);
                a[im][1] = f2tf32(ap[8 * LDA + k0 + tig]);
                a[im][2] = f2tf32(ap[k0 + tig + 4]);
                a[im][3] = f2tf32(ap[8 * LDA + k0 + tig + 4]);
            }
#pragma unroll
            for (int in = 0; in < 2; in++) {
                const int nc = nb + in * 8 + g;
                b[in][0] = f2tf32(bs[(k0 + tig) * LDB + nc]);
                b[in][1] = f2tf32(bs[(k0 + tig + 4) * LDB + nc]);
            }
#pragma unroll
            for (int im = 0; im < 2; im++)
#pragma unroll
                for (int in = 0; in < 2; in++)
                    mma_tf32(acc[im][in], a[im], b[in]);
        }
        __syncthreads();
    }

    const int mb = warp_m * 32;
    const int nb = warp_n * 16;
#pragma unroll
    for (int im = 0; im < 2; im++) {
#pragma unroll
        for (int in = 0; in < 2; in++) {
            const int row = m0 + mb + im * 16 + g;
            const int col = n0 + nb + in * 8 + tig * 2;
            float2 o0 = make_float2(acc[im][in][0], acc[im][in][1]);
            float2 o1 = make_float2(acc[im][in][2], acc[im][in][3]);
            if (addend) {
                const float2 r0 = *(const float2*)&addend[(long)row * N + col];
                const float2 r1 = *(const float2*)&addend[(long)(row + 8) * N + col];
                o0.x += r0.x; o0.y += r0.y;
                o1.x += r1.x; o1.y += r1.y;
            }
            *(float2*)&C[(long)row * N + col] = o0;
            *(float2*)&C[(long)(row + 8) * N + col] = o1;
        }
    }
}

// Two independent 1024x512x512 jobs selected by blockIdx.z
struct Job {
    const float* A;
    const float* B;
    const float* bias;
    float* C;
};

__global__ __launch_bounds__(128) void gemm2(Job j0, Job j1)
{
    Job j = (blockIdx.z == 0) ? j0 : j1;
    gemm_core(j.A, Ddim, j.B, Ddim, Ddim, j.bias, nullptr, j.C, Ddim,
              blockIdx.y * 64, blockIdx.x * 64);
}

// Final: out[b] = attn[b] @ pre1[b] + pre2[b]   (256 x 512, K=256 per batch)
__global__ __launch_bounds__(256) void gemm_fin(
    const float* __restrict__ attn, const float* __restrict__ pre1,
    const float* __restrict__ pre2, float* __restrict__ out)
{
    const int z = blockIdx.z;
    gemm_core_256(attn + (long)z * Tdim * Sdim, Sdim,
                  pre1 + (long)z * Sdim * Ddim, Ddim, Sdim,
                  pre2 + (long)z * Tdim * Ddim,
                  out + (long)z * Tdim * Ddim, Ddim,
                  blockIdx.y * 64, blockIdx.x * 64);
}

// ---------------------------------------------------------------------------
// score[b,t,s] = sum_d v[d] * tanh(wq[b,t,d] + uh[b,s,d])   (MUFU-bound)
// ---------------------------------------------------------------------------
__global__ __launch_bounds__(256) void score_kernel(
    const float* __restrict__ wq, const float* __restrict__ uh,
    const float* __restrict__ v, float* __restrict__ sc)
{
    __shared__ float Aq[32][33];
    __shared__ float Au[32][33];
    __shared__ float vs[32];

    const int b = blockIdx.z;
    const int t0 = blockIdx.y * 32;
    const int s0 = blockIdx.x * 32;
    const int tid = threadIdx.x;
    const int tx = tid & 15, ty = tid >> 4;

    const float* wqb = wq + ((long)b * Tdim + t0) * Ddim;
    const float* uhb = uh + ((long)b * Sdim + s0) * Ddim;

    const int lr = tid >> 3;
    const int lc = (tid & 7) << 2;

    float acc00 = 0.f, acc01 = 0.f, acc10 = 0.f, acc11 = 0.f;

    for (int d0 = 0; d0 < Ddim; d0 += 32) {
        float4 q = *(const float4*)&wqb[(long)lr * Ddim + d0 + lc];
        Aq[lc + 0][lr] = q.x;
        Aq[lc + 1][lr] = q.y;
        Aq[lc + 2][lr] = q.z;
        Aq[lc + 3][lr] = q.w;
        float4 u = *(const float4*)&uhb[(long)lr * Ddim + d0 + lc];
        Au[lc + 0][lr] = u.x;
        Au[lc + 1][lr] = u.y;
        Au[lc + 2][lr] = u.z;
        Au[lc + 3][lr] = u.w;
        if (tid < 32) vs[tid] = v[d0 + tid];
        __syncthreads();

#pragma unroll
        for (int dk = 0; dk < 32; dk++) {
            float vv = vs[dk];
            float a0 = Aq[dk][ty * 2 + 0];
            float a1 = Aq[dk][ty * 2 + 1];
            float u0 = Au[dk][tx * 2 + 0];
            float u1 = Au[dk][tx * 2 + 1];
            acc00 += vv * tanh_fast(a0 + u0);
            acc01 += vv * tanh_fast(a0 + u1);
            acc10 += vv * tanh_fast(a1 + u0);
            acc11 += vv * tanh_fast(a1 + u1);
        }
        __syncthreads();
    }

    float* scp = sc + ((long)b * Tdim + t0) * Sdim + s0;
    scp[(long)(ty * 2 + 0) * Sdim + tx * 2 + 0] = acc00;
    scp[(long)(ty * 2 + 0) * Sdim + tx * 2 + 1] = acc01;
    scp[(long)(ty * 2 + 1) * Sdim + tx * 2 + 0] = acc10;
    scp[(long)(ty * 2 + 1) * Sdim + tx * 2 + 1] = acc11;
}

// ---------------------------------------------------------------------------
// Masked softmax: warp-per-row, 8 rows/block (reference semantics).
// ---------------------------------------------------------------------------
__global__ __launch_bounds__(256) void softmax_kernel(
    float* __restrict__ sc, const int* __restrict__ mask,
    float* __restrict__ attn_out)
{
    const int warp = threadIdx.x >> 5;
    const int lane = threadIdx.x & 31;
    const int row = blockIdx.x * 8 + warp;
    const int b = row >> 8;

    float* rp = sc + (long)row * Sdim;
    const int* mp = mask + b * Sdim;

    float x[8];
    float m = -1e30f;
#pragma unroll
    for (int i = 0; i < 8; i++) {
        x[i] = rp[i * 32 + lane];
        m = fmaxf(m, x[i]);
    }
#pragma unroll
    for (int o = 16; o > 0; o >>= 1)
        m = fmaxf(m, __shfl_xor_sync(0xffffffffu, m, o));

    float e[8];
    float sum = 0.f;
#pragma unroll
    for (int i = 0; i < 8; i++) {
        float keep = 1.0f - (float)mp[i * 32 + lane];
        e[i] = __expf(x[i] - m) * keep;
        sum += e[i];
    }
#pragma unroll
    for (int o = 16; o > 0; o >>= 1)
        sum += __shfl_xor_sync(0xffffffffu, sum, o);

    const float inv = 1.0f / sum;
    float* ap = attn_out ? attn_out + (long)row * Sdim : nullptr;
#pragma unroll
    for (int i = 0; i < 8; i++) {
        float a = e[i] * inv;
        rp[i * 32 + lane] = a;
        if (ap) ap[i * 32 + lane] = a;
    }
}

// ---------------------------------------------------------------------------
extern "C" void kernel_launch(void* const* d_in, const int* in_sizes, int n_in,
                              void* d_out, int out_size)
{
    const float* out_in = (const float*)d_in[0];  // (B,T,D)
    const float* ctx    = (const float*)d_in[1];  // (B,S,D)
    const int*   mask   = (const int*)d_in[2];    // (B,S)
    const float* Wq     = (const float*)d_in[3];  // (D,D)
    const float* bq     = (const float*)d_in[4];  // (D,)
    const float* Wc     = (const float*)d_in[5];  // (D,D)
    const float* v      = (const float*)d_in[6];  // (D,)
    const float* Wout   = (const float*)d_in[7];  // (2D,D)
    const float* bout   = (const float*)d_in[8];  // (D,)

    float *p_wq, *p_uh, *p_sc, *p_pre1, *p_pre2;
    cudaGetSymbolAddress((void**)&p_wq, g_wq);
    cudaGetSymbolAddress((void**)&p_uh, g_uh);
    cudaGetSymbolAddress((void**)&p_sc, g_sc);
    cudaGetSymbolAddress((void**)&p_pre1, g_pre1);
    cudaGetSymbolAddress((void**)&p_pre2, g_pre2);

    const long BTD = (long)Bdim * Tdim * Ddim;  // 524288
    const long BTS = (long)Bdim * Tdim * Sdim;  // 262144
    float* out_f = (float*)d_out;
    float* attn_out = ((long)out_size >= BTD + BTS) ? (out_f + BTD) : nullptr;

    Job j0{out_in, Wq, bq, p_wq};                          // wq
    Job j1{ctx, Wc, nullptr, p_uh};                        // uh
    Job j2{ctx, Wout, nullptr, p_pre1};                    // pre1
    Job j3{out_in, Wout + (long)Ddim * Ddim, bout, p_pre2};// pre2

    const dim3 g2(Ddim / 64, (Bdim * Tdim) / 64, 2);

    // Fork: side stream computes pre1/pre2 concurrently with wq/uh+score.
    cudaStream_t s1;
    cudaStreamCreateWithFlags(&s1, cudaStreamNonBlocking);
    cudaEvent_t ev0, ev1;
    cudaEventCreateWithFlags(&ev0, cudaEventDisableTiming);
    cudaEventCreateWithFlags(&ev1, cudaEventDisableTiming);

    cudaEventRecord(ev0, 0);
    cudaStreamWaitEvent(s1, ev0, 0);
    gemm2<<<g2, 128, 0, s1>>>(j2, j3);     // pre1, pre2 (branch B)
    cudaEventRecord(ev1, s1);

    gemm2<<<g2, 128>>>(j0, j1);            // wq, uh (branch A)
    score_kernel<<<dim3(Sdim / 32, Tdim / 32, Bdim), 256>>>(p_wq, p_uh, v, p_sc);
    softmax_kernel<<<(Bdim * Tdim) / 8, 256>>>(p_sc, mask, attn_out);

    cudaStreamWaitEvent(0, ev1, 0);        // join
    gemm_fin<<<dim3(Ddim / 64, Tdim / 64, Bdim), 256>>>(p_sc, p_pre1, p_pre2, out_f);
}